// round 16
// baseline (speedup 1.0000x reference)
#include <cuda_runtime.h>

#define DT 0.005f

// ---------------- scratch (no allocation allowed) ----------------
__device__ float    g_partials[4096];
__device__ unsigned g_sem = 0;
__device__ float4   g_coef[8192];   // fallback path only

// fallback float2 swizzle
__device__ __forceinline__ int swz(int t)  { return t ^ ((t >> 4) & 15); }
// float4 swizzle
__device__ __forceinline__ int swz4(int s) { return s ^ ((s >> 3) & 7); }

__device__ __forceinline__ void cp16(unsigned dst, const void* src) {
    asm volatile("cp.async.cg.shared.global [%0], [%1], 16;\n" :: "r"(dst), "l"(src));
}
__device__ __forceinline__ void cp_commit() { asm volatile("cp.async.commit_group;\n"); }
template <int N>
__device__ __forceinline__ void cp_wait() { asm volatile("cp.async.wait_group %0;\n" :: "n"(N)); }

// ============================================================================
// Split-row kernel, fused quadratic loss (NO pass 3). Grid 2B=1024, 128 thr.
// Loss of a steady chunk is quadratic in the scan-provided entry state ve:
//   sum (Ploc_i - DT*W_i + u_i*ve)^2 = A0 + 2*A1.ve + A2*|ve|^2,  u_i=dkp*g^i
// so pass1 streams pred+targ ONCE accumulating (A0, A1x, A1y) alongside the
// scan affine; after the scan each chunk's loss is 5 FMAs. Deletes the Ploc
// write-back, s_ve round-trip, pass 3, and one barrier. Main path: [A],[B].
//   g0 = pred S0 (+halo), g1 = pred S1, g2 = targ S0 (swizzled)
//   targ S1 read in pass1 via per-thread LDG.128 (L1 absorbs line replays)
// Transient t<64 exact via table + post-scan replay (threads j<8, half 0).
// smem ~26.3KB, 7 CTAs/SM -> 1036 slots >= 1024 -> single wave.
// ============================================================================
__global__ void __launch_bounds__(128, 7)
kf_split(const float* __restrict__ pred, const float* __restrict__ targ,
         const float* __restrict__ qv_p, const float* __restrict__ r_p,
         float* __restrict__ out, int B)
{
    constexpr int NT    = 128;
    constexpr int CHUNK = 8;             // steps per thread per sub-tile
    constexpr int SUB   = 512;           // pairs per sub-tile (1024 steps)
    constexpr int NPREF = 32;            // halo pairs (64 timesteps)
    constexpr int TTR   = 64;            // transient gain length
    constexpr int NTC   = TTR / CHUNK;   // 8 transient chunks

    __shared__ float4 sz[2 * SUB + NPREF];  // [0,512) S0, [512,1024) S1, halo
    __shared__ float4 st4[SUB];             // targ S0 pairs (swizzled)
    __shared__ float4 s_tc[TTR];            // transient (g, kv, u, inv)
    __shared__ float2 s_tb[NTC];            // per-chunk b-affine (Gb, Hb)
    __shared__ float2 s_vinit;              // halo-derived entry v (half 1)
    __shared__ float  sWG[2][4], sWBx[2][4], sWBy[2][4];
    __shared__ float  sred[4];
    __shared__ int    s_last;

    const int j    = threadIdx.x;
    const int blk  = blockIdx.x;
    const int row  = blk >> 1;
    const int half = blk & 1;
    const int lane = j & 31;
    const int wrp  = j >> 5;

    const float qv = __ldg(qv_p);
    const float r  = __ldg(r_p);

    const unsigned sa = (unsigned)__cvta_generic_to_shared(sz);
    const unsigned ta = (unsigned)__cvta_generic_to_shared(st4);

    // ---- cp.async: g0 = pred S0 (+halo), g1 = pred S1, g2 = targ S0 ----
    const float4* gp4 = (const float4*)pred + (size_t)row * 2048
                      + (size_t)half * 1024;
    #pragma unroll
    for (int k = 0; k < 4; ++k) {
        int l = j + k * NT;
        cp16(sa + 16u * (unsigned)swz4(l), gp4 + l);
    }
    if (half == 1 && j < NPREF)             // halo = global pairs [-32,0)
        cp16(sa + 16u * (unsigned)(2 * SUB + swz4(j)), gp4 - NPREF + j);
    cp_commit();                             // group 0
    #pragma unroll
    for (int k = 0; k < 4; ++k) {
        int l = j + k * NT;
        cp16(sa + 16u * (unsigned)(SUB + swz4(l)), gp4 + SUB + l);
    }
    cp_commit();                             // group 1
    const float4* gt4 = (const float4*)targ + (size_t)row * 2048
                      + (size_t)half * 1024;
    #pragma unroll
    for (int k = 0; k < 4; ++k) {
        int l = j + k * NT;
        cp16(ta + 16u * (unsigned)swz4(l), gt4 + l);
    }
    cp_commit();                             // group 2

    // ---- steady-state constants, per-thread ----
    const float cstar = 0.5f * (sqrtf(fmaf(qv, qv, 4.f * r * qv)) - qv);
    const float cps   = cstar + qv;
    const float invs  = 1.0f / (cps + r);
    const float kvs   = cps * invs;
    const float gs    = 1.0f - kvs;
    const float us    = DT * cstar * invs;
    const float kps   = us / kvs;            // kp* = u*/(1-g*)
    const float dkp   = DT - kps;
    const float gg2 = gs * gs, gg4 = gg2 * gg2;
    const float gg8 = gg4 * gg4;             // g^CHUNK
    // A2 = dkp^2 * sum_{i=0}^{7} g^{2i}  (Horner, no divide)
    float ssum = 1.f;
    #pragma unroll
    for (int k = 0; k < 7; ++k) ssum = fmaf(ssum, gg2, 1.f);
    const float A2c = dkp * dkp * ssum;

    const bool trans = (half == 0) && (j < NTC);

    // ---- transient gain table + per-chunk b-affine (half 0, j<8) ----
    if (trans) {
        const float r64   = 64.f * r;
        const float rqv64 = 64.f * r * qv;
        const float qvr   = qv + r;
        const float qvr64 = 64.f * qvr;
        const int tstart  = j * CHUNK;
        float p = 1.f, q = 1.f;               // c0 = 1
        #pragma unroll 1
        for (int s = 0; s < tstart; ++s) {
            float pn = fmaf(r64, p, rqv64 * q);
            float qn = fmaf(qvr64, q, 64.f * p);
            p = pn; q = qn;
        }
        float Gb = 1.f, Hb = 0.f;             // b' = g*b + r*u
        #pragma unroll 1
        for (int i = 0; i < CHUNK; ++i) {
            float num  = fmaf(qv,  q, p);
            float den  = fmaf(qvr, q, p);
            float invd = 1.0f / den;
            float kv   = num * invd;
            float inv  = q * invd;
            float u    = DT * p * invd;
            float g    = 1.0f - kv;
            s_tc[tstart + i] = make_float4(g, kv, u, inv);
            Hb = fmaf(g, Hb, r * u);
            Gb *= g;
            float pn = fmaf(r64, p, rqv64 * q);
            float qn = fmaf(qvr64, q, 64.f * p);
            p = pn; q = qn;
        }
        s_tb[j] = make_float2(Gb, Hb);
    }

    cp_wait<0>();                             // all staged data landed
    __syncthreads();                          // [A]

    // ---- half 1: parallel halo dot product on warp 0 ----
    if (half == 1 && wrp == 0) {
        float lg = log2f(gs);
        float e0 = (float)(63 - 2 * lane);
        float w0h = kvs * exp2f(e0 * lg);
        float w1h = kvs * exp2f((e0 - 1.f) * lg);
        float4 Z = sz[2 * SUB + swz4(lane)];
        float hx = fmaf(w0h, Z.x, w1h * Z.z);
        float hy = fmaf(w0h, Z.y, w1h * Z.w);
        #pragma unroll
        for (int o = 16; o; o >>= 1) {
            hx += __shfl_down_sync(0xffffffffu, hx, o);
            hy += __shfl_down_sync(0xffffffffu, hy, o);
        }
        if (lane == 0) s_vinit = make_float2(hx, hy);
    }

    const int p0 = 4 * j;                     // first local pair of my chunk

    // ---- pass 1, sub-tile 0: scan affine (+ fused loss partials if steady) ----
    float G0, Bx0 = 0.f, By0 = 0.f;
    float A00 = 0.f, A1x0 = 0.f, A1y0 = 0.f;
    if (trans) {
        G0 = 1.f;
        const int t0 = j * CHUNK;
        #pragma unroll
        for (int i = 0; i < 4; ++i) {
            float4 Z  = sz[swz4(p0 + i)];
            float4 c0 = s_tc[t0 + 2 * i];
            float4 c1 = s_tc[t0 + 2 * i + 1];
            Bx0 = fmaf(c0.x, Bx0, c0.y * Z.x);
            By0 = fmaf(c0.x, By0, c0.y * Z.y);
            Bx0 = fmaf(c1.x, Bx0, c1.y * Z.z);
            By0 = fmaf(c1.x, By0, c1.y * Z.w);
            G0 *= c0.x * c1.x;
        }
    } else {
        G0 = gg8;
        float uw = dkp;                       // u_i = dkp * g^i
        #pragma unroll
        for (int i = 0; i < 4; ++i) {
            float4 Z = sz[swz4(p0 + i)];
            float4 W = st4[swz4(p0 + i)];
            // step 2i
            float ex = fmaf(kps, Z.x, fmaf(dkp, Bx0, -DT * W.x));
            float ey = fmaf(kps, Z.y, fmaf(dkp, By0, -DT * W.y));
            A00  = fmaf(ex, ex, fmaf(ey, ey, A00));
            A1x0 = fmaf(uw, ex, A1x0);
            A1y0 = fmaf(uw, ey, A1y0);
            Bx0 = fmaf(gs, Bx0, kvs * Z.x);
            By0 = fmaf(gs, By0, kvs * Z.y);
            uw *= gs;
            // step 2i+1
            float ex1 = fmaf(kps, Z.z, fmaf(dkp, Bx0, -DT * W.z));
            float ey1 = fmaf(kps, Z.w, fmaf(dkp, By0, -DT * W.w));
            A00  = fmaf(ex1, ex1, fmaf(ey1, ey1, A00));
            A1x0 = fmaf(uw, ex1, A1x0);
            A1y0 = fmaf(uw, ey1, A1y0);
            Bx0 = fmaf(gs, Bx0, kvs * Z.z);
            By0 = fmaf(gs, By0, kvs * Z.w);
            uw *= gs;
        }
    }

    // ---- pass 1, sub-tile 1: always steady; targ via gmem LDG ----
    float G1 = gg8, Bx1 = 0.f, By1 = 0.f;
    float A01 = 0.f, A1x1 = 0.f, A1y1 = 0.f;
    {
        const float4* gw = gt4 + SUB + p0;
        float uw = dkp;
        #pragma unroll
        for (int i = 0; i < 4; ++i) {
            float4 Z = sz[SUB + swz4(p0 + i)];
            float4 W = gw[i];
            float ex = fmaf(kps, Z.x, fmaf(dkp, Bx1, -DT * W.x));
            float ey = fmaf(kps, Z.y, fmaf(dkp, By1, -DT * W.y));
            A01  = fmaf(ex, ex, fmaf(ey, ey, A01));
            A1x1 = fmaf(uw, ex, A1x1);
            A1y1 = fmaf(uw, ey, A1y1);
            Bx1 = fmaf(gs, Bx1, kvs * Z.x);
            By1 = fmaf(gs, By1, kvs * Z.y);
            uw *= gs;
            float ex1 = fmaf(kps, Z.z, fmaf(dkp, Bx1, -DT * W.z));
            float ey1 = fmaf(kps, Z.w, fmaf(dkp, By1, -DT * W.w));
            A01  = fmaf(ex1, ex1, fmaf(ey1, ey1, A01));
            A1x1 = fmaf(uw, ex1, A1x1);
            A1y1 = fmaf(uw, ey1, A1y1);
            Bx1 = fmaf(gs, Bx1, kvs * Z.z);
            By1 = fmaf(gs, By1, kvs * Z.w);
            uw *= gs;
        }
    }

    // ---- intra-warp scans for both sub-tiles (interleaved ILP) ----
    #pragma unroll
    for (int off = 1; off < 32; off <<= 1) {
        float pG0  = __shfl_up_sync(0xffffffffu, G0,  off);
        float pBx0 = __shfl_up_sync(0xffffffffu, Bx0, off);
        float pBy0 = __shfl_up_sync(0xffffffffu, By0, off);
        float pG1  = __shfl_up_sync(0xffffffffu, G1,  off);
        float pBx1 = __shfl_up_sync(0xffffffffu, Bx1, off);
        float pBy1 = __shfl_up_sync(0xffffffffu, By1, off);
        if (lane >= off) {
            Bx0 = fmaf(G0, pBx0, Bx0);
            By0 = fmaf(G0, pBy0, By0);
            G0 *= pG0;
            Bx1 = fmaf(G1, pBx1, Bx1);
            By1 = fmaf(G1, pBy1, By1);
            G1 *= pG1;
        }
    }
    float eG0  = __shfl_up_sync(0xffffffffu, G0,  1);
    float eBx0 = __shfl_up_sync(0xffffffffu, Bx0, 1);
    float eBy0 = __shfl_up_sync(0xffffffffu, By0, 1);
    float eG1  = __shfl_up_sync(0xffffffffu, G1,  1);
    float eBx1 = __shfl_up_sync(0xffffffffu, Bx1, 1);
    float eBy1 = __shfl_up_sync(0xffffffffu, By1, 1);
    if (lane == 0) {
        eG0 = 1.f; eBx0 = 0.f; eBy0 = 0.f;
        eG1 = 1.f; eBx1 = 0.f; eBy1 = 0.f;
    }
    if (lane == 31) {
        sWG[0][wrp] = G0; sWBx[0][wrp] = Bx0; sWBy[0][wrp] = By0;
        sWG[1][wrp] = G1; sWBx[1][wrp] = Bx1; sWBy[1][wrp] = By1;
    }
    __syncthreads();                          // [B] partials + vinit ready

    // ---- fold: S0 entry, S0 total -> S1 entry ----
    float vinx = 0.f, viny = 0.f;
    if (half == 1) { float2 vi = s_vinit; vinx = vi.x; viny = vi.y; }

    float Gp0 = 1.f, Bpx0 = 0.f, Bpy0 = 0.f;
    float Gp1 = 1.f, Bpx1 = 0.f, Bpy1 = 0.f;
    float Gt = 1.f, Bxt = 0.f, Byt = 0.f;
    #pragma unroll
    for (int k = 0; k < 4; ++k) {
        float wg0 = sWG[0][k], wbx0 = sWBx[0][k], wby0 = sWBy[0][k];
        if (k < wrp) {
            Bpx0 = fmaf(wg0, Bpx0, wbx0);
            Bpy0 = fmaf(wg0, Bpy0, wby0);
            Gp0 *= wg0;
            float wg1 = sWG[1][k];
            Bpx1 = fmaf(wg1, Bpx1, sWBx[1][k]);
            Bpy1 = fmaf(wg1, Bpy1, sWBy[1][k]);
            Gp1 *= wg1;
        }
        Bxt = fmaf(wg0, Bxt, wbx0);           // S0 total (all 4 warps)
        Byt = fmaf(wg0, Byt, wby0);
        Gt *= wg0;
    }
    float Ge0 = eG0 * Gp0;
    float vx0 = fmaf(Ge0, vinx, fmaf(eG0, Bpx0, eBx0));  // S0 chunk entry
    float vy0 = fmaf(Ge0, viny, fmaf(eG0, Bpy0, eBy0));
    float ven1x = fmaf(Gt, vinx, Bxt);                   // v at end of S0
    float ven1y = fmaf(Gt, viny, Byt);
    float Ge1 = eG1 * Gp1;
    float vx1 = fmaf(Ge1, ven1x, fmaf(eG1, Bpx1, eBx1)); // S1 chunk entry
    float vy1 = fmaf(Ge1, ven1y, fmaf(eG1, Bpy1, eBy1));

    // ---- finalize loss ----
    float acc = 0.f;
    if (trans) {
        // exact replay for t in [8j, 8j+8) using smem pred + smem targ
        float b = 0.f;
        #pragma unroll
        for (int k = 0; k < NTC - 1; ++k) {
            if (k < j) { float2 tb = s_tb[k]; b = fmaf(tb.x, b, tb.y); }
        }
        const int t0 = j * CHUNK;
        float vx = vx0, vy = vy0;
        #pragma unroll 1
        for (int i = 0; i < 4; ++i) {
            float4 Z  = sz[swz4(p0 + i)];
            float4 W  = st4[swz4(p0 + i)];
            float4 c0 = s_tc[t0 + 2 * i];
            float4 c1 = s_tc[t0 + 2 * i + 1];
            float kp0 = fmaf(b, c0.w, c0.z);  b = r * kp0;
            float dx0 = Z.x - vx, dy0 = Z.y - vy;
            if (j != 0 || i != 0) {           // global t = 0 has no loss term
                float ex = fmaf(-DT, W.x, fmaf(kp0, dx0, DT * vx));
                float ey = fmaf(-DT, W.y, fmaf(kp0, dy0, DT * vy));
                acc = fmaf(ex, ex, fmaf(ey, ey, acc));
            }
            vx = fmaf(c0.y, dx0, vx); vy = fmaf(c0.y, dy0, vy);
            float kp1 = fmaf(b, c1.w, c1.z);  b = r * kp1;
            float dx1 = Z.z - vx, dy1 = Z.w - vy;
            float ex1 = fmaf(-DT, W.z, fmaf(kp1, dx1, DT * vx));
            float ey1 = fmaf(-DT, W.w, fmaf(kp1, dy1, DT * vy));
            acc = fmaf(ex1, ex1, fmaf(ey1, ey1, acc));
            vx = fmaf(c1.y, dx1, vx); vy = fmaf(c1.y, dy1, vy);
        }
    } else {
        // quadratic closure: A0 + 2*A1.ve + A2*|ve|^2
        float lin0 = fmaf(A1x0, vx0, A1y0 * vy0);
        float qd0  = fmaf(vx0, vx0, vy0 * vy0);
        acc = fmaf(A2c, qd0, fmaf(2.f, lin0, A00));
    }
    {
        float lin1 = fmaf(A1x1, vx1, A1y1 * vy1);
        float qd1  = fmaf(vx1, vx1, vy1 * vy1);
        acc += fmaf(A2c, qd1, fmaf(2.f, lin1, A01));
    }

    // ---- block reduce -> partial ----
    #pragma unroll
    for (int o = 16; o; o >>= 1) acc += __shfl_down_sync(0xffffffffu, acc, o);
    if (lane == 0) sred[wrp] = acc;
    __syncthreads();
    if (j == 0) {
        float v = sred[0] + sred[1] + sred[2] + sred[3];
        g_partials[blk] = v;
        __threadfence();
        unsigned done = atomicAdd(&g_sem, 1u);
        s_last = (done == (unsigned)gridDim.x - 1u);
    }
    __syncthreads();

    // ---- last CTA: deterministic final reduction + semaphore reset ----
    if (s_last) {
        __threadfence();
        float* sf = (float*)s_tc;             // reuse table region (done)
        const int nblk = 2 * B;
        float v = 0.f;
        for (int i = j; i < nblk; i += NT) v += g_partials[i];
        sf[j] = v;
        __syncthreads();
        for (int o = 64; o; o >>= 1) {
            if (j < o) sf[j] += sf[j + o];
            __syncthreads();
        }
        if (j == 0) {
            out[0] = sf[0] / ((float)B * 4095.0f * 2.f);
            atomicExch(&g_sem, 0u);
        }
    }
}

// ============================================================================
// Fallback path (any T) — proven Round-1 kernels
// ============================================================================
__global__ void kf_setup(const float* __restrict__ q_vel_p,
                         const float* __restrict__ r_vel_p, int T) {
    __shared__ float skp[4096];
    __shared__ float skv[4096];
    __shared__ int   s_conv;
    __shared__ float s_kp_last, s_kv_last;

    int Tser = T < 4096 ? T : 4096;
    if (threadIdx.x == 0) {
        float qvv = *q_vel_p;
        float rr  = *r_vel_p;
        float bb = 0.f, cc = 1.f;
        float kp = 0.f, kv = 0.f;
        int tconv = Tser;
        for (int t = 0; t < Tser; ++t) {
            float cp  = cc + qvv;
            float bp  = fmaf(DT, cc, bb);
            float S   = cp + rr;
            float inv = __fdividef(1.f, S);
            kv = cp * inv;
            kp = bp * inv;
            skp[t] = kp; skv[t] = kv;
            float rs = rr * inv;
            float nc = cp * rs;
            float nb = bp * rs;
            if (nc == cc && nb == bb) { tconv = t + 1; break; }
            cc = nc; bb = nb;
        }
        s_conv = tconv; s_kp_last = kp; s_kv_last = kv;
    }
    __syncthreads();
    int   tconv = s_conv;
    float kpl = s_kp_last, kvl = s_kv_last;
    for (int t = threadIdx.x; t < T; t += blockDim.x) {
        float kp = (t < tconv) ? skp[t] : kpl;
        float kv = (t < tconv) ? skv[t] : kvl;
        g_coef[t] = make_float4(1.f - kv, kv, DT - kp, kp);
    }
}

__global__ void __launch_bounds__(256)
kf_main(const float* __restrict__ pred, const float* __restrict__ targ, int T) {
    extern __shared__ float2 sp2[];
    const int NT = 256;
    int j = threadIdx.x, bb = blockIdx.x;

    const float4* gp = (const float4*)(pred + (size_t)bb * T * 2);
    int n4 = (T * 2) / 4;
    for (int m = j; m < n4; m += NT) {
        float4 v = gp[m];
        sp2[swz(2 * m)]     = make_float2(v.x, v.y);
        sp2[swz(2 * m + 1)] = make_float2(v.z, v.w);
    }
    __syncthreads();

    int chunk = (T + NT - 1) / NT;
    int t0 = j * chunk;

    float A = 1.f, Bx = 0.f, By = 0.f;
    for (int i = 0; i < chunk; ++i) {
        int t = t0 + i;
        if (t >= T) break;
        float4 cf = g_coef[t];
        float2 z  = sp2[swz(t)];
        A  = A * cf.x;
        Bx = fmaf(cf.x, Bx, cf.y * z.x);
        By = fmaf(cf.x, By, cf.y * z.y);
    }

    __shared__ float sA[256], sBx[256], sBy[256];
    sA[j] = A; sBx[j] = Bx; sBy[j] = By;
    __syncthreads();
    for (int off = 1; off < NT; off <<= 1) {
        float a2 = 0.f, bx2 = 0.f, by2 = 0.f;
        bool act = (j >= off);
        if (act) {
            float ap = sA[j - off], bxp = sBx[j - off], byp = sBy[j - off];
            a2  = A * ap;
            bx2 = fmaf(A, bxp, Bx);
            by2 = fmaf(A, byp, By);
        }
        __syncthreads();
        if (act) { A = a2; Bx = bx2; By = by2; sA[j] = A; sBx[j] = Bx; sBy[j] = By; }
        __syncthreads();
    }
    float vx = (j == 0) ? 0.f : sBx[j - 1];
    float vy = (j == 0) ? 0.f : sBy[j - 1];

    const float2* gt2 = (const float2*)(targ + (size_t)bb * T * 2);
    float acc = 0.f;
    for (int i = 0; i < chunk; ++i) {
        int t = t0 + i;
        if (t >= T) break;
        float4 cf = g_coef[t];
        float2 z  = sp2[swz(t)];
        if (t > 0) {
            float2 w = gt2[t];
            float ex = fmaf(cf.z, vx, fmaf(cf.w, z.x, -DT * w.x));
            float ey = fmaf(cf.z, vy, fmaf(cf.w, z.y, -DT * w.y));
            acc = fmaf(ex, ex, fmaf(ey, ey, acc));
        }
        vx = fmaf(cf.x, vx, cf.y * z.x);
        vy = fmaf(cf.x, vy, cf.y * z.y);
    }

    for (int o = 16; o; o >>= 1) acc += __shfl_down_sync(0xffffffffu, acc, o);
    __shared__ float swsum[8];
    if ((j & 31) == 0) swsum[j >> 5] = acc;
    __syncthreads();
    if (j < 8) {
        float v = swsum[j];
        v += __shfl_down_sync(0xffu, v, 4);
        v += __shfl_down_sync(0xffu, v, 2);
        v += __shfl_down_sync(0xffu, v, 1);
        if (j == 0) g_partials[bb] = v;
    }
}

__global__ void kf_reduce(float* __restrict__ out, int B, int T) {
    __shared__ float s[256];
    float v = 0.f;
    for (int i = threadIdx.x; i < B; i += blockDim.x) v += g_partials[i];
    s[threadIdx.x] = v;
    __syncthreads();
    for (int o = 128; o; o >>= 1) {
        if (threadIdx.x < o) s[threadIdx.x] += s[threadIdx.x + o];
        __syncthreads();
    }
    if (threadIdx.x == 0)
        out[0] = s[0] / ((float)B * (float)(T - 1) * 2.f);
}

extern "C" void kernel_launch(void* const* d_in, const int* in_sizes, int n_in,
                              void* d_out, int out_size) {
    // metadata order: pred_vel, targ_vel, q_pos, q_vel, r_vel, p0
    const float* pred  = (const float*)d_in[0];
    const float* targ  = (const float*)d_in[1];
    const float* q_vel = (const float*)d_in[3];
    const float* r_vel = (const float*)d_in[4];
    int B = in_sizes[5] / 2;          // p0 is (B, 2)
    int T = in_sizes[0] / (B * 2);    // pred_vel is (B, T, 2)

    if (T == 4096 && B >= 1 && B <= 2048) {
        kf_split<<<2 * B, 128>>>(pred, targ, q_vel, r_vel, (float*)d_out, B);
    } else {
        kf_setup<<<1, 256>>>(q_vel, r_vel, T);
        size_t sh = (size_t)T * sizeof(float2);
        kf_main<<<B, 256, sh>>>(pred, targ, T);
        kf_reduce<<<1, 256>>>((float*)d_out, B, T);
    }
}